// round 1
// baseline (speedup 1.0000x reference)
#include <cuda_runtime.h>
#include <cuda_bf16.h>

// Problem constants
#define BATCH 64
#define NPTS  512
#define CH    1024
#define KNN   32

// GEMM tiling
#define BT 128   // output tile (M=N)
#define KT 32    // k tile

// Scratch (allocation-free rule: __device__ globals)
__device__ float g_S[(size_t)BATCH * NPTS * NPTS];      // 64 MB similarity
__device__ float g_thr[BATCH * NPTS];                   // per-row 32nd-largest
__device__ float g_dinv[BATCH * NPTS];                  // deg^-1/2

// ---------------------------------------------------------------------------
// Kernel 1: S[b] = X[b] @ X[b]^T   (batched, fp32, 128x128x32 tiles)
// grid = (4, 4, 64), block = 256 threads, 8x8 microtile per thread
// ---------------------------------------------------------------------------
__global__ __launch_bounds__(256) void xxt_kernel(const float* __restrict__ x) {
    __shared__ float As[KT][BT + 4];
    __shared__ float Bs[KT][BT + 4];

    const int b  = blockIdx.z;
    const int ti = blockIdx.y * BT;   // row block
    const int tj = blockIdx.x * BT;   // col block
    const float* X = x + (size_t)b * NPTS * CH;

    const int tid = threadIdx.x;
    const int tx  = tid & 15;         // 0..15 -> 8 cols each
    const int ty  = tid >> 4;         // 0..15 -> 8 rows each

    float acc[8][8];
#pragma unroll
    for (int i = 0; i < 8; i++)
#pragma unroll
        for (int j = 0; j < 8; j++) acc[i][j] = 0.f;

    for (int k0 = 0; k0 < CH; k0 += KT) {
        // Load 128x32 of A and B. 1024 float4 per operand / 256 threads = 4 each.
#pragma unroll
        for (int l = 0; l < 4; l++) {
            const int fid = tid + l * 256;     // 0..1023
            const int row = fid >> 3;          // 0..127
            const int kq  = fid & 7;           // which float4 along k
            float4 va = *(const float4*)(X + (size_t)(ti + row) * CH + k0 + kq * 4);
            As[kq * 4 + 0][row] = va.x;
            As[kq * 4 + 1][row] = va.y;
            As[kq * 4 + 2][row] = va.z;
            As[kq * 4 + 3][row] = va.w;
            float4 vb = *(const float4*)(X + (size_t)(tj + row) * CH + k0 + kq * 4);
            Bs[kq * 4 + 0][row] = vb.x;
            Bs[kq * 4 + 1][row] = vb.y;
            Bs[kq * 4 + 2][row] = vb.z;
            Bs[kq * 4 + 3][row] = vb.w;
        }
        __syncthreads();

#pragma unroll 8
        for (int k = 0; k < KT; k++) {
            float a[8], bv[8];
            *(float4*)&a[0]  = *(const float4*)&As[k][ty * 8];
            *(float4*)&a[4]  = *(const float4*)&As[k][ty * 8 + 4];
            *(float4*)&bv[0] = *(const float4*)&Bs[k][tx * 8];
            *(float4*)&bv[4] = *(const float4*)&Bs[k][tx * 8 + 4];
#pragma unroll
            for (int i = 0; i < 8; i++)
#pragma unroll
                for (int j = 0; j < 8; j++)
                    acc[i][j] = fmaf(a[i], bv[j], acc[i][j]);
        }
        __syncthreads();
    }

    float* Sb = g_S + (size_t)b * NPTS * NPTS;
#pragma unroll
    for (int i = 0; i < 8; i++) {
        const int r = ti + ty * 8 + i;
        float* dst = Sb + (size_t)r * NPTS + tj + tx * 8;
        *(float4*)(dst)     = make_float4(acc[i][0], acc[i][1], acc[i][2], acc[i][3]);
        *(float4*)(dst + 4) = make_float4(acc[i][4], acc[i][5], acc[i][6], acc[i][7]);
    }
}

// ---------------------------------------------------------------------------
// Kernel 2: per row (b,i): bitonic sort 512 values ascending, thr = s[480]
// (32nd largest), degree = count(S >= thr), store thr and deg^-1/2.
// grid = 64*512 blocks, 256 threads, 2 elements per thread.
// ---------------------------------------------------------------------------
__global__ __launch_bounds__(256) void thresh_deg_kernel() {
    __shared__ float s[NPTS];
    __shared__ int cnt;

    const int row = blockIdx.x;                  // b*512 + i
    const float* Srow = g_S + (size_t)row * NPTS;
    const int t = threadIdx.x;

    s[t]       = Srow[t];
    s[t + 256] = Srow[t + 256];
    if (t == 0) cnt = 0;
    __syncthreads();

    for (int k = 2; k <= NPTS; k <<= 1) {
        for (int j = k >> 1; j > 0; j >>= 1) {
#pragma unroll
            for (int u = 0; u < 2; u++) {
                const int i = t + u * 256;
                const int l = i ^ j;
                if (l > i) {
                    float a = s[i], c = s[l];
                    const bool up = ((i & k) == 0);
                    if (up ? (a > c) : (a < c)) { s[i] = c; s[l] = a; }
                }
            }
            __syncthreads();
        }
    }

    const float th = s[NPTS - KNN];  // 32nd largest
    int c = (int)(s[t] >= th) + (int)(s[t + 256] >= th);
#pragma unroll
    for (int off = 16; off > 0; off >>= 1)
        c += __shfl_down_sync(0xFFFFFFFFu, c, off);
    if ((t & 31) == 0) atomicAdd(&cnt, c);
    __syncthreads();

    if (t == 0) {
        g_thr[row]  = th;
        g_dinv[row] = rsqrtf((float)cnt);
    }
}

// ---------------------------------------------------------------------------
// Kernel 3: out[b,i,j] = (S >= thr[b,i]) * dinv[b,i] * dinv[b,j]
// float4 vectorized streaming pass.
// ---------------------------------------------------------------------------
__global__ __launch_bounds__(256) void finalize_kernel(float* __restrict__ out) {
    const size_t q = (size_t)blockIdx.x * blockDim.x + threadIdx.x;   // float4 index
    const size_t base = q * 4;                                        // element index
    const int rowIdx = (int)(base >> 9);        // b*512 + i
    const int j = (int)(base & 511);
    const int b = rowIdx >> 9;

    const float th = g_thr[rowIdx];
    const float di = g_dinv[rowIdx];
    const float4 s4 = *(const float4*)(g_S + base);
    const float4 d4 = *(const float4*)(g_dinv + (b << 9) + j);

    float4 o;
    o.x = (s4.x >= th) ? di * d4.x : 0.f;
    o.y = (s4.y >= th) ? di * d4.y : 0.f;
    o.z = (s4.z >= th) ? di * d4.z : 0.f;
    o.w = (s4.w >= th) ? di * d4.w : 0.f;
    *(float4*)(out + base) = o;
}

// ---------------------------------------------------------------------------
extern "C" void kernel_launch(void* const* d_in, const int* in_sizes, int n_in,
                              void* d_out, int out_size) {
    const float* x = (const float*)d_in[0];
    float* out = (float*)d_out;

    dim3 g1(NPTS / BT, NPTS / BT, BATCH);      // (4,4,64)
    xxt_kernel<<<g1, 256>>>(x);

    thresh_deg_kernel<<<BATCH * NPTS, 256>>>();

    const size_t total4 = (size_t)BATCH * NPTS * NPTS / 4;   // 4,194,304
    finalize_kernel<<<(unsigned)(total4 / 256), 256>>>(out);
}

// round 6
// speedup vs baseline: 1.1544x; 1.1544x over previous
#include <cuda_runtime.h>
#include <cuda_bf16.h>

// Problem constants
#define BATCH 64
#define NPTS  512
#define CH    1024
#define KNN   32

// GEMM tiling
#define BT 128   // output tile (M=N)
#define KT 32    // k tile

// Scratch (allocation-free rule: __device__ globals)
__device__ float g_S[(size_t)BATCH * NPTS * NPTS];      // 64 MB similarity
__device__ float g_thr[BATCH * NPTS];                   // per-row 32nd-largest
__device__ float g_dinv[BATCH * NPTS];                  // deg^-1/2

// packed fp32x2 FMA (Blackwell FFMA2) — each lane is exact fp32 fma
#define FFMA2(D, A, B) asm("fma.rn.f32x2 %0, %1, %2, %0;" : "+l"(D) : "l"(A), "l"(B))

__device__ __forceinline__ unsigned long long pack_dup(float x) {
    unsigned long long r;
    asm("mov.b64 %0, {%1, %1};" : "=l"(r) : "r"(__float_as_uint(x)));
    return r;
}
__device__ __forceinline__ float lo_f(unsigned long long v) { return __uint_as_float((unsigned)v); }
__device__ __forceinline__ float hi_f(unsigned long long v) { return __uint_as_float((unsigned)(v >> 32)); }

// Decode upper-triangular pair (bi<=bj, 4x4 grid, 10 tiles) from linear id,
// branch-free: tiles enumerated row-major: (0,0..3),(1,1..3),(2,2..3),(3,3).
__device__ __forceinline__ void tri_decode(int t, int& bi, int& bj) {
    // row starts: 0,4,7,9
    bi = (t >= 4) + (t >= 7) + (t >= 9);
    const int start = bi * 4 - ((bi * (bi - 1)) >> 1);   // 0,4,7,9
    bj = bi + (t - start);
}

// ---------------------------------------------------------------------------
// Kernel 1: S[b] = X[b] @ X[b]^T, upper-triangular blocks only, mirrored.
// grid = (10, 1, 64), block = 256 threads, 8x8 microtile, FFMA2 inner loop.
// ---------------------------------------------------------------------------
__global__ __launch_bounds__(256, 2) void xxt_kernel(const float* __restrict__ x) {
    __shared__ float As[KT][BT + 4];
    __shared__ float Bs[KT][BT + 4];

    const int b = blockIdx.z;
    int bi, bj;
    tri_decode((int)blockIdx.x, bi, bj);
    const int ti = bi * BT;           // row block
    const int tj = bj * BT;           // col block
    const float* X = x + (size_t)b * NPTS * CH;

    const int tid = threadIdx.x;
    const int tx  = tid & 15;         // 8 cols each
    const int ty  = tid >> 4;         // 8 rows each

    unsigned long long acc[8][4];     // 8 rows x 4 col-pairs, packed fp32x2
#pragma unroll
    for (int i = 0; i < 8; i++)
#pragma unroll
        for (int j = 0; j < 4; j++) acc[i][j] = 0ull;

    for (int k0 = 0; k0 < CH; k0 += KT) {
#pragma unroll
        for (int l = 0; l < 4; l++) {
            const int fid = tid + l * 256;     // 0..1023
            const int row = fid >> 3;          // 0..127
            const int kq  = fid & 7;           // which float4 along k
            float4 va = *(const float4*)(X + (size_t)(ti + row) * CH + k0 + kq * 4);
            As[kq * 4 + 0][row] = va.x;
            As[kq * 4 + 1][row] = va.y;
            As[kq * 4 + 2][row] = va.z;
            As[kq * 4 + 3][row] = va.w;
            float4 vb = *(const float4*)(X + (size_t)(tj + row) * CH + k0 + kq * 4);
            Bs[kq * 4 + 0][row] = vb.x;
            Bs[kq * 4 + 1][row] = vb.y;
            Bs[kq * 4 + 2][row] = vb.z;
            Bs[kq * 4 + 3][row] = vb.w;
        }
        __syncthreads();

#pragma unroll 8
        for (int k = 0; k < KT; k++) {
            // b pairs: 8 consecutive floats -> 4 packed f32x2 (two 16B LDS)
            ulonglong2 b01 = *(const ulonglong2*)&Bs[k][tx * 8];
            ulonglong2 b23 = *(const ulonglong2*)&Bs[k][tx * 8 + 4];
            float4 a03 = *(const float4*)&As[k][ty * 8];
            float4 a47 = *(const float4*)&As[k][ty * 8 + 4];
            unsigned long long aa[8];
            aa[0] = pack_dup(a03.x); aa[1] = pack_dup(a03.y);
            aa[2] = pack_dup(a03.z); aa[3] = pack_dup(a03.w);
            aa[4] = pack_dup(a47.x); aa[5] = pack_dup(a47.y);
            aa[6] = pack_dup(a47.z); aa[7] = pack_dup(a47.w);
#pragma unroll
            for (int i = 0; i < 8; i++) {
                FFMA2(acc[i][0], aa[i], b01.x);
                FFMA2(acc[i][1], aa[i], b01.y);
                FFMA2(acc[i][2], aa[i], b23.x);
                FFMA2(acc[i][3], aa[i], b23.y);
            }
        }
        __syncthreads();
    }

    float* Sb = g_S + (size_t)b * NPTS * NPTS;

    // normal store (row-major at (ti, tj))
#pragma unroll
    for (int i = 0; i < 8; i++) {
        const int r = ti + ty * 8 + i;
        float* dst = Sb + (size_t)r * NPTS + tj + tx * 8;
        *(float4*)(dst) = make_float4(lo_f(acc[i][0]), hi_f(acc[i][0]),
                                      lo_f(acc[i][1]), hi_f(acc[i][1]));
        *(float4*)(dst + 4) = make_float4(lo_f(acc[i][2]), hi_f(acc[i][2]),
                                          lo_f(acc[i][3]), hi_f(acc[i][3]));
    }

    // mirrored store for off-diagonal blocks: S[c, r] = S[r, c]
    if (bi != bj) {
#pragma unroll
        for (int j = 0; j < 8; j++) {
            float v[8];
#pragma unroll
            for (int i = 0; i < 8; i++) {
                unsigned long long p = acc[i][j >> 1];
                v[i] = (j & 1) ? hi_f(p) : lo_f(p);
            }
            const int c = tj + tx * 8 + j;
            float* dst = Sb + (size_t)c * NPTS + ti + ty * 8;
            *(float4*)(dst)     = make_float4(v[0], v[1], v[2], v[3]);
            *(float4*)(dst + 4) = make_float4(v[4], v[5], v[6], v[7]);
        }
    }
}

// ---------------------------------------------------------------------------
// Kernel 2: per row, exact 32nd-largest via bitwise radix select on
// order-preserving uint keys; one warp per row, 16 values/lane in registers.
// ---------------------------------------------------------------------------
__global__ __launch_bounds__(256) void select_kernel() {
    const int warp = (blockIdx.x * blockDim.x + threadIdx.x) >> 5;   // row id
    const int lane = threadIdx.x & 31;
    const float* Srow = g_S + (size_t)warp * NPTS;

    unsigned u[16];
#pragma unroll
    for (int j = 0; j < 16; j++) {
        unsigned bbits = __float_as_uint(Srow[j * 32 + lane]);
        u[j] = (bbits & 0x80000000u) ? ~bbits : (bbits | 0x80000000u);
    }

    // largest v with count(u >= v) >= KNN  ==  exact key of 32nd-largest
    unsigned prefix = 0;
#pragma unroll
    for (int bit = 31; bit >= 0; bit--) {
        const unsigned cand = prefix | (1u << bit);
        int c = 0;
#pragma unroll
        for (int j = 0; j < 16; j++) c += (u[j] >= cand);
        c = __reduce_add_sync(0xFFFFFFFFu, c);
        if (c >= KNN) prefix = cand;
    }

    int deg = 0;
#pragma unroll
    for (int j = 0; j < 16; j++) deg += (u[j] >= prefix);
    deg = __reduce_add_sync(0xFFFFFFFFu, deg);

    if (lane == 0) {
        g_thr[warp]  = __uint_as_float((prefix & 0x80000000u) ? (prefix ^ 0x80000000u)
                                                              : ~prefix);
        g_dinv[warp] = rsqrtf((float)deg);
    }
}

// ---------------------------------------------------------------------------
// Kernel 3: out[b,i,j] = (S >= thr[b,i]) * dinv[b,i] * dinv[b,j]
// ---------------------------------------------------------------------------
__global__ __launch_bounds__(256) void finalize_kernel(float* __restrict__ out) {
    const size_t q = (size_t)blockIdx.x * blockDim.x + threadIdx.x;   // float4 index
    const size_t base = q * 4;
    const int rowIdx = (int)(base >> 9);        // b*512 + i
    const int j = (int)(base & 511);
    const int b = rowIdx >> 9;

    const float th = g_thr[rowIdx];
    const float di = g_dinv[rowIdx];
    const float4 s4 = *(const float4*)(g_S + base);
    const float4 d4 = *(const float4*)(g_dinv + (b << 9) + j);

    float4 o;
    o.x = (s4.x >= th) ? di * d4.x : 0.f;
    o.y = (s4.y >= th) ? di * d4.y : 0.f;
    o.z = (s4.z >= th) ? di * d4.z : 0.f;
    o.w = (s4.w >= th) ? di * d4.w : 0.f;
    *(float4*)(out + base) = o;
}

// ---------------------------------------------------------------------------
extern "C" void kernel_launch(void* const* d_in, const int* in_sizes, int n_in,
                              void* d_out, int out_size) {
    const float* x = (const float*)d_in[0];
    float* out = (float*)d_out;

    dim3 g1(10, 1, BATCH);                      // 10 upper-tri blocks x 64 batches
    xxt_kernel<<<g1, 256>>>(x);

    select_kernel<<<(BATCH * NPTS) / 8, 256>>>();   // 8 warps/block, 1 row/warp

    const size_t total4 = (size_t)BATCH * NPTS * NPTS / 4;
    finalize_kernel<<<(unsigned)(total4 / 256), 256>>>(out);
}

// round 7
// speedup vs baseline: 1.8774x; 1.6263x over previous
#include <cuda_runtime.h>
#include <cuda_bf16.h>

// Problem constants
#define BATCH 64
#define NPTS  512
#define CH    1024
#define KNN   32

// GEMM tiling: 128 (rows) x 64 (cols) tiles, KT=32 k-slice
#define BTM 128
#define BTN 64
#define KT  32

// Scratch (allocation-free rule: __device__ globals)
__device__ float g_S[(size_t)BATCH * NPTS * NPTS];      // 64 MB similarity
__device__ float g_thr[BATCH * NPTS];                   // per-row 32nd-largest
__device__ float g_dinv[BATCH * NPTS];                  // deg^-1/2

// ---------------------------------------------------------------------------
// Kernel 1: S[b] = X[b] @ X[b]^T, upper-triangular coverage with 128x64 tiles.
// Tile (bi, cj) computed iff cj >= 2*bi  (20 tiles per batch).
// Every upper-tri element is computed directly; a lower-tri element (R,C) is
// written by mirroring (C,R) iff it is NOT directly computed, i.e. iff
// floor(C/64) < 2*floor(R/128)  — this is exactly the per-thread predicate
// (2*bi + rhalf) < (cj & ~1). Exactly-once coverage, no write races.
// grid = (20, 64), block = 256 threads, 8x4 microtile, scalar FFMA.
// ---------------------------------------------------------------------------
__global__ __launch_bounds__(256, 3) void xxt_kernel(const float* __restrict__ x) {
    __shared__ float As[KT][BTM + 4];
    __shared__ float Bs[KT][BTN + 4];

    const int t = blockIdx.x;                 // 0..19
    const int b = blockIdx.y;
    const int bi = (t >= 8) + (t >= 14) + (t >= 18);
    const int cj = t - bi * (9 - bi) + 2 * bi;    // start(bi) = bi*(9-bi)
    const int ti = bi * BTM;                  // row offset
    const int tj = cj * BTN;                  // col offset
    const float* X = x + (size_t)b * NPTS * CH;

    const int tid = threadIdx.x;
    const int tx  = tid & 15;                 // 16 threads x 4 cols = 64
    const int ty  = tid >> 4;                 // 16 threads x 8 rows = 128

    float acc[8][4];
#pragma unroll
    for (int i = 0; i < 8; i++)
#pragma unroll
        for (int j = 0; j < 4; j++) acc[i][j] = 0.f;

    for (int k0 = 0; k0 < CH; k0 += KT) {
        // A tile: 128 rows x 32 k = 1024 float4 -> 4 per thread
#pragma unroll
        for (int l = 0; l < 4; l++) {
            const int fid = tid + l * 256;     // 0..1023
            const int row = fid >> 3;          // 0..127
            const int kq  = fid & 7;
            float4 v = *(const float4*)(X + (size_t)(ti + row) * CH + k0 + kq * 4);
            As[kq * 4 + 0][row] = v.x;
            As[kq * 4 + 1][row] = v.y;
            As[kq * 4 + 2][row] = v.z;
            As[kq * 4 + 3][row] = v.w;
        }
        // B tile: 64 rows x 32 k = 512 float4 -> 2 per thread
#pragma unroll
        for (int l = 0; l < 2; l++) {
            const int fid = tid + l * 256;     // 0..511
            const int row = fid >> 3;          // 0..63
            const int kq  = fid & 7;
            float4 v = *(const float4*)(X + (size_t)(tj + row) * CH + k0 + kq * 4);
            Bs[kq * 4 + 0][row] = v.x;
            Bs[kq * 4 + 1][row] = v.y;
            Bs[kq * 4 + 2][row] = v.z;
            Bs[kq * 4 + 3][row] = v.w;
        }
        __syncthreads();

#pragma unroll 8
        for (int k = 0; k < KT; k++) {
            float a[8], bv[4];
            *(float4*)&a[0] = *(const float4*)&As[k][ty * 8];
            *(float4*)&a[4] = *(const float4*)&As[k][ty * 8 + 4];
            *(float4*)&bv[0] = *(const float4*)&Bs[k][tx * 4];
#pragma unroll
            for (int i = 0; i < 8; i++)
#pragma unroll
                for (int j = 0; j < 4; j++)
                    acc[i][j] = fmaf(a[i], bv[j], acc[i][j]);
        }
        __syncthreads();
    }

    float* Sb = g_S + (size_t)b * NPTS * NPTS;

    // direct store: one float4 per row
#pragma unroll
    for (int i = 0; i < 8; i++) {
        const int r = ti + ty * 8 + i;
        *(float4*)(Sb + (size_t)r * NPTS + tj + tx * 4) =
            make_float4(acc[i][0], acc[i][1], acc[i][2], acc[i][3]);
    }

    // mirror store: S[c][r] for elements whose transpose target tile is not
    // directly computed. rhalf constant per thread (rows ty*8..ty*8+7 are in
    // one 64-row half since ty*8+7 < 64 <=> ty < 8).
    const int rhalf = (ty >= 8);
    if ((2 * bi + rhalf) < (cj & ~1)) {
#pragma unroll
        for (int j = 0; j < 4; j++) {
            const int c = tj + tx * 4 + j;
            float* dst = Sb + (size_t)c * NPTS + ti + ty * 8;
            *(float4*)(dst)     = make_float4(acc[0][j], acc[1][j], acc[2][j], acc[3][j]);
            *(float4*)(dst + 4) = make_float4(acc[4][j], acc[5][j], acc[6][j], acc[7][j]);
        }
    }
}

// ---------------------------------------------------------------------------
// Kernel 2: per row, exact 32nd-largest via bitwise radix select on
// order-preserving uint keys; one warp per row, 16 values/lane in registers.
// ---------------------------------------------------------------------------
__global__ __launch_bounds__(256) void select_kernel() {
    const int warp = (blockIdx.x * blockDim.x + threadIdx.x) >> 5;   // row id
    const int lane = threadIdx.x & 31;
    const float* Srow = g_S + (size_t)warp * NPTS;

    unsigned u[16];
#pragma unroll
    for (int j = 0; j < 16; j++) {
        unsigned bbits = __float_as_uint(Srow[j * 32 + lane]);
        u[j] = (bbits & 0x80000000u) ? ~bbits : (bbits | 0x80000000u);
    }

    // largest v with count(u >= v) >= KNN  ==  exact key of 32nd-largest
    unsigned prefix = 0;
#pragma unroll
    for (int bit = 31; bit >= 0; bit--) {
        const unsigned cand = prefix | (1u << bit);
        int c = 0;
#pragma unroll
        for (int j = 0; j < 16; j++) c += (u[j] >= cand);
        c = __reduce_add_sync(0xFFFFFFFFu, c);
        if (c >= KNN) prefix = cand;
    }

    int deg = 0;
#pragma unroll
    for (int j = 0; j < 16; j++) deg += (u[j] >= prefix);
    deg = __reduce_add_sync(0xFFFFFFFFu, deg);

    if (lane == 0) {
        g_thr[warp]  = __uint_as_float((prefix & 0x80000000u) ? (prefix ^ 0x80000000u)
                                                              : ~prefix);
        g_dinv[warp] = rsqrtf((float)deg);
    }
}

// ---------------------------------------------------------------------------
// Kernel 3: out[b,i,j] = (S >= thr[b,i]) * dinv[b,i] * dinv[b,j]
// ---------------------------------------------------------------------------
__global__ __launch_bounds__(256) void finalize_kernel(float* __restrict__ out) {
    const size_t q = (size_t)blockIdx.x * blockDim.x + threadIdx.x;   // float4 index
    const size_t base = q * 4;
    const int rowIdx = (int)(base >> 9);        // b*512 + i
    const int j = (int)(base & 511);
    const int b = rowIdx >> 9;

    const float th = g_thr[rowIdx];
    const float di = g_dinv[rowIdx];
    const float4 s4 = *(const float4*)(g_S + base);
    const float4 d4 = *(const float4*)(g_dinv + (b << 9) + j);

    float4 o;
    o.x = (s4.x >= th) ? di * d4.x : 0.f;
    o.y = (s4.y >= th) ? di * d4.y : 0.f;
    o.z = (s4.z >= th) ? di * d4.z : 0.f;
    o.w = (s4.w >= th) ? di * d4.w : 0.f;
    *(float4*)(out + base) = o;
}

// ---------------------------------------------------------------------------
extern "C" void kernel_launch(void* const* d_in, const int* in_sizes, int n_in,
                              void* d_out, int out_size) {
    const float* x = (const float*)d_in[0];
    float* out = (float*)d_out;

    dim3 g1(20, BATCH);                         // 20 tri-tiles x 64 batches
    xxt_kernel<<<g1, 256>>>(x);

    select_kernel<<<(BATCH * NPTS) / 8, 256>>>();   // 8 warps/block, 1 row/warp

    const size_t total4 = (size_t)BATCH * NPTS * NPTS / 4;
    finalize_kernel<<<(unsigned)(total4 / 256), 256>>>(out);
}